// round 14
// baseline (speedup 1.0000x reference)
#include <cuda_runtime.h>
#include <cstdint>

// IntMLP on B200, baseline sm_100 PTX target (no tcgen05 in this harness).
// Inputs: int32 words (robust conversion handles f32 too). Output: float32.
// out = clipdiv(clipdiv(x @ w1^T, 720) @ w2^T, 1440), exact int32 math.
//
// R13 -> R14: PERSISTENT CTAs + cross-tile cp.async pipelining. Evidence:
// GEMM2 (4 waves) runs at the compute floor; GEMM1 (14 waves) pays ~10K cyc
// per wave in prologue-ramp/drain. Persistent grid (2 CTAs/SM) keeps the
// 3-stage ring rolling across tile boundaries: one cold prologue per CTA,
// epilogues overlap next tile's in-flight loads.

#define TOKENS 8192
#define HIDDEN 2048
#define FFDIM  8192

// ---------------- device scratch (no allocs allowed) ----------------
__device__ __align__(256) int8_t g_X [(size_t)TOKENS * HIDDEN];
__device__ __align__(256) int8_t g_W1[(size_t)FFDIM  * HIDDEN];
__device__ __align__(256) int8_t g_W2[(size_t)HIDDEN * FFDIM ];
__device__ __align__(256) int8_t g_H [(size_t)TOKENS * FFDIM ];   // 64MB

// ------------------------- tiling config -------------------------
static constexpr int BM = 128;
static constexpr int BN = 128;
static constexpr int BKB = 128;                     // K elems (int8) per stage
static constexpr int STAGES = 3;
static constexpr int A_TILE = BM * BKB;             // 16384
static constexpr int B_TILE = BN * BKB;             // 16384
static constexpr uint32_t SMEM_BYTES = STAGES * (A_TILE + B_TILE);  // 98304
static constexpr int GROUP_M = 8;

// ------------------------- PTX helpers -------------------------
__device__ __forceinline__ uint32_t s2u(const void* p) {
    uint32_t a;
    asm("{ .reg .u64 t; cvta.to.shared.u64 t, %1; cvt.u32.u64 %0, t; }"
        : "=r"(a) : "l"(p));
    return a;
}

#define CP_ASYNC16(dst, src) \
    asm volatile("cp.async.cg.shared.global [%0], [%1], 16;" :: "r"(dst), "l"(src))
#define CP_COMMIT() asm volatile("cp.async.commit_group;" ::: "memory")
#define CP_WAIT(n)  asm volatile("cp.async.wait_group %0;" :: "n"(n) : "memory")

#define LDM_X4(r0, r1, r2, r3, addr) \
    asm volatile("ldmatrix.sync.aligned.m8n8.x4.shared.b16 {%0,%1,%2,%3}, [%4];" \
        : "=r"(r0), "=r"(r1), "=r"(r2), "=r"(r3) : "r"(addr))

#define MMA_S8(c, a, b0, b1) \
    asm("mma.sync.aligned.m16n8k32.row.col.s32.s8.s8.s32 " \
        "{%0,%1,%2,%3}, {%4,%5,%6,%7}, {%8,%9}, {%0,%1,%2,%3};" \
        : "+r"((c)[0]), "+r"((c)[1]), "+r"((c)[2]), "+r"((c)[3]) \
        : "r"((a)[0]), "r"((a)[1]), "r"((a)[2]), "r"((a)[3]), "r"(b0), "r"(b1))

// 16B-chunk XOR swizzle within a 128B row: conflict-free cp.async + ldmatrix.
__device__ __forceinline__ uint32_t sw(uint32_t row, uint32_t kb) {
    return row * 128u + (((((kb >> 4) ^ row) & 7u)) << 4) + (kb & 15u);
}

// python floor-div by positive constant + clip to [-127, 127]
template<int DIV>
__device__ __forceinline__ int fd(int a) {
    int q = a / DIV;
    q -= (int)((a % DIV != 0) && (a < 0));
    q = q < -127 ? -127 : q;
    q = q >  127 ?  127 : q;
    return q;
}

// ------------------------- GEMM kernel -------------------------
// Persistent: each CTA walks tiles t = bid, bid+grid, ... with the cp.async
// stage ring rolling continuously across tile boundaries.
// C = clipdiv(A[M,K]i8 @ B[N,K]i8^T, DIV); C int8 (layer 1) or f32 (layer 2).
template<int DIV, bool F32OUT, int NK>
__global__ void __launch_bounds__(128, 2)
gemm_i8(const int8_t* __restrict__ A, const int8_t* __restrict__ B,
        void* __restrict__ Cp, int M, int N, int K, int total_tiles)
{
    extern __shared__ char smem[];
    const uint32_t sA = s2u(smem);                  // STAGES * A_TILE
    const uint32_t sB = sA + STAGES * A_TILE;       // STAGES * B_TILE

    const int tid  = threadIdx.x;
    const int lane = tid & 31;
    const int wid  = tid >> 5;
    const int wm = (wid >> 1) * 64;     // 2 warp-rows
    const int wn = (wid & 1) * 64;      // 2 warp-cols
    const int tiles_m = M / BM, tiles_n = N / BN;

    // GROUP_M supertile rasterization (runs once per tile switch)
    auto rast = [&](int t, int& mt, int& nt) {
        const int group = GROUP_M * tiles_n;
        int gi    = t / group;
        int first = gi * GROUP_M;
        int gsz   = min(tiles_m - first, GROUP_M);
        int inb   = t - gi * group;
        mt = first + (inb % gsz);
        nt = inb / gsz;
    };

    // stage loader for tile (mt,nt), K-offset k0, stage st
    auto issue = [&](int mt, int nt, int k0, int st) {
        const int8_t* Ab = A + (size_t)mt * BM * K;
        const int8_t* Bb = B + (size_t)nt * BN * K;
        const uint32_t dA = sA + st * A_TILE;
        const uint32_t dB = sB + st * B_TILE;
        #pragma unroll
        for (int u = 0; u < 8; u++) {
            int idx = tid + 128 * u;
            int row = idx >> 3;
            int kb  = (idx & 7) << 4;
            CP_ASYNC16(dA + sw(row, kb), Ab + (size_t)row * K + k0 + kb);
        }
        #pragma unroll
        for (int u = 0; u < 8; u++) {
            int idx = tid + 128 * u;
            int row = idx >> 3;
            int kb  = (idx & 7) << 4;
            CP_ASYNC16(dB + sw(row, kb), Bb + (size_t)row * K + k0 + kb);
        }
    };

    int t = blockIdx.x;
    if (t >= total_tiles) return;
    int mt, nt;
    rast(t, mt, nt);

    // prologue: first two stages of the first tile (NK >= 16 > STAGES-1)
    issue(mt, nt, 0,   0); CP_COMMIT();
    issue(mt, nt, BKB, 1); CP_COMMIT();

    int c[4][8][4];                                 // 64x64 -> 4 m16 x 8 n8
    #pragma unroll
    for (int i = 0; i < 4; i++)
        #pragma unroll
        for (int j = 0; j < 8; j++)
            #pragma unroll
            for (int r = 0; r < 4; r++) c[i][j][r] = 0;

    const uint32_t a_row0 = wm + (lane & 15);
    const uint32_t a_kbx  = (uint32_t)((lane >> 4) << 4);
    const uint32_t b_row0 = wn + ((lane >> 4) << 3) + (lane & 7);
    const uint32_t b_kbx  = (uint32_t)(((lane >> 3) & 1) << 4);

    const int NCT = gridDim.x;
    int st_c = 0;                       // stage to consume
    int st_l = STAGES - 1;              // stage for next load

    for (;;) {
        const int tn = t + NCT;
        const bool have_next = (tn < total_tiles);
        int mtn = 0, ntn = 0;
        if (have_next) rast(tn, mtn, ntn);

        for (int kt = 0; kt < NK; kt++) {
            // invariant: exactly one commit per iteration (incl. prologue 2)
            // => CP_WAIT(STAGES-2) guarantees the consumed stage is complete.
            CP_WAIT(STAGES - 2);
            __syncthreads();

            const uint32_t bA = sA + st_c * A_TILE;
            const uint32_t bB = sB + st_c * B_TILE;

            #pragma unroll
            for (int ks = 0; ks < 4; ks++) {
                uint32_t a[4][4], b[4][4];
                #pragma unroll
                for (int mti = 0; mti < 4; mti++) {     // A: 4 x m16k32
                    uint32_t ad = bA + sw(a_row0 + mti * 16, ks * 32 + a_kbx);
                    LDM_X4(a[mti][0], a[mti][1], a[mti][2], a[mti][3], ad);
                }
                #pragma unroll
                for (int nh = 0; nh < 4; nh++) {        // B: 4 x n16k32
                    uint32_t bd = bB + sw(b_row0 + nh * 16, ks * 32 + b_kbx);
                    LDM_X4(b[nh][0], b[nh][1], b[nh][2], b[nh][3], bd);
                }
                if (ks == 0) {
                    // lookahead load: k-iter kt+STAGES-1, possibly next tile
                    const int gk = kt + (STAGES - 1);
                    if (gk < NK)          issue(mt,  nt,  gk * BKB,        st_l);
                    else if (have_next)   issue(mtn, ntn, (gk - NK) * BKB, st_l);
                    CP_COMMIT();    // always exactly one commit
                }
                #pragma unroll
                for (int mti = 0; mti < 4; mti++)
                    #pragma unroll
                    for (int nti = 0; nti < 8; nti++)
                        MMA_S8(c[mti][nti], a[mti],
                               b[nti >> 1][(nti & 1) * 2],
                               b[nti >> 1][(nti & 1) * 2 + 1]);
            }
            st_c = (st_c == STAGES - 1) ? 0 : st_c + 1;
            st_l = (st_l == STAGES - 1) ? 0 : st_l + 1;
        }

        // ---- epilogue for tile (mt, nt): register/global only, overlaps
        //      the next tile's in-flight cp.async loads ----
        {
            const size_t crow = (size_t)mt * BM + wm;
            const int    ccol = nt * BN + wn;
            #pragma unroll
            for (int mti = 0; mti < 4; mti++) {
                #pragma unroll
                for (int nti = 0; nti < 8; nti++) {
                    size_t r0  = crow + mti * 16 + (lane >> 2);
                    int    col = ccol + nti * 8 + (lane & 3) * 2;
                    if (F32OUT) {
                        float* Cf = (float*)Cp;
                        float2 v0 = make_float2((float)fd<DIV>(c[mti][nti][0]),
                                                (float)fd<DIV>(c[mti][nti][1]));
                        float2 v1 = make_float2((float)fd<DIV>(c[mti][nti][2]),
                                                (float)fd<DIV>(c[mti][nti][3]));
                        *(float2*)&Cf[r0 * (size_t)N + col] = v0;
                        *(float2*)&Cf[(r0 + 8) * (size_t)N + col] = v1;
                    } else {
                        int8_t* Ci = (int8_t*)Cp;
                        int q0 = fd<DIV>(c[mti][nti][0]), q1 = fd<DIV>(c[mti][nti][1]);
                        int q2 = fd<DIV>(c[mti][nti][2]), q3 = fd<DIV>(c[mti][nti][3]);
                        *(uint16_t*)&Ci[r0 * (size_t)N + col] =
                            (uint16_t)((q0 & 0xFF) | ((q1 & 0xFF) << 8));
                        *(uint16_t*)&Ci[(r0 + 8) * (size_t)N + col] =
                            (uint16_t)((q2 & 0xFF) | ((q3 & 0xFF) << 8));
                    }
                }
            }
        }

        if (!have_next) break;
        // reset accumulators for the next tile
        #pragma unroll
        for (int i = 0; i < 4; i++)
            #pragma unroll
            for (int j = 0; j < 8; j++)
                #pragma unroll
                for (int r = 0; r < 4; r++) c[i][j][r] = 0;
        t = tn; mt = mtn; nt = ntn;
    }
}

// -------- dtype-robust 32-bit-word -> i8 conversion (3 tensors, 1 launch) ----
__device__ __forceinline__ int8_t word_to_i8(uint32_t u) {
    float f = __uint_as_float(u);
    float t = truncf(f);
    bool isf = (fabsf(f) <= 127.0f) && (f == t);   // NaN fails both safely
    int v = isf ? (int)f : (int)u;
    return (int8_t)v;
}

__global__ void cvt_w32_i8_3(const uint4* __restrict__ in0, char4* __restrict__ out0,
                             const uint4* __restrict__ in1, char4* __restrict__ out1,
                             const uint4* __restrict__ in2, char4* __restrict__ out2,
                             int n4) {
    int i = blockIdx.x * blockDim.x + threadIdx.x;
    const uint4* in;
    char4* out;
    int j = i;
    if (i < n4)              { in = in0; out = out0; }
    else if (i < 2 * n4)     { in = in1; out = out1; j = i - n4; }
    else if (i < 3 * n4)     { in = in2; out = out2; j = i - 2 * n4; }
    else return;
    uint4 w = in[j];
    char4 c;
    c.x = word_to_i8(w.x);
    c.y = word_to_i8(w.y);
    c.z = word_to_i8(w.z);
    c.w = word_to_i8(w.w);
    out[j] = c;
}

// ------------------------- host -------------------------
extern "C" void kernel_launch(void* const* d_in, const int* in_sizes, int n_in,
                              void* d_out, int out_size) {
    void *pX, *pW1, *pW2, *pH;
    cudaGetSymbolAddress(&pX,  g_X);
    cudaGetSymbolAddress(&pW1, g_W1);
    cudaGetSymbolAddress(&pW2, g_W2);
    cudaGetSymbolAddress(&pH,  g_H);

    const int n  = TOKENS * HIDDEN;      // all three tensors: 16.7M elements
    const int n4 = n / 4;
    const int cb = (3 * n4 + 255) / 256;
    cvt_w32_i8_3<<<cb, 256>>>((const uint4*)d_in[0], (char4*)pX,
                              (const uint4*)d_in[1], (char4*)pW1,
                              (const uint4*)d_in[2], (char4*)pW2, n4);

    int sms = 148;
    cudaDeviceGetAttribute(&sms, cudaDevAttrMultiProcessorCount, 0);
    const int slots = 2 * sms;

    cudaFuncSetAttribute(gemm_i8<720,  false, HIDDEN / BKB>,
                         cudaFuncAttributeMaxDynamicSharedMemorySize, SMEM_BYTES);
    cudaFuncSetAttribute(gemm_i8<1440, true,  FFDIM / BKB>,
                         cudaFuncAttributeMaxDynamicSharedMemorySize, SMEM_BYTES);

    // GEMM1: h[8192,8192]i8 = clipdiv(x @ w1^T, 720); tiles = 64*64 = 4096
    {
        const int total = (TOKENS / BM) * (FFDIM / BN);
        const int grid  = slots < total ? slots : total;
        gemm_i8<720, false, HIDDEN / BKB><<<grid, 128, SMEM_BYTES>>>(
            (const int8_t*)pX, (const int8_t*)pW1, pH,
            TOKENS, FFDIM, HIDDEN, total);
    }
    // GEMM2: out[8192,2048]f32 = clipdiv(h @ w2^T, 1440); tiles = 64*16 = 1024
    {
        const int total = (TOKENS / BM) * (HIDDEN / BN);
        const int grid  = slots < total ? slots : total;
        gemm_i8<1440, true, FFDIM / BKB><<<grid, 128, SMEM_BYTES>>>(
            (const int8_t*)pH, (const int8_t*)pW2, d_out,
            TOKENS, HIDDEN, FFDIM, total);
    }
}

// round 15
// speedup vs baseline: 1.0320x; 1.0320x over previous
#include <cuda_runtime.h>
#include <cstdint>

// IntMLP on B200, baseline sm_100 PTX target (no tcgen05 in this harness).
// Inputs: int32 words (robust conversion handles f32 too). Output: float32.
// out = clipdiv(clipdiv(x @ w1^T, 720) @ w2^T, 1440), exact int32 math.
//
// R14 -> R15: revert persistent (regressed). Back to R12/13 (744us) + ONE
// change: cross-CTA phase offset. Each SMSP's two warps belong to the two
// co-resident CTAs (1 warp/SMSP per CTA); those CTAs are wave-synchronized
// and phase-locked, so both hit LDSM-latency head stalls simultaneously.
// Odd-residency-slot CTAs spin ~2000 cyc (half a k-iter period) at start;
// no cross-CTA barrier exists, so the offset persists and the paired warps
// cover each other's LDSM phases with MMAs.

#define TOKENS 8192
#define HIDDEN 2048
#define FFDIM  8192

// ---------------- device scratch (no allocs allowed) ----------------
__device__ __align__(256) int8_t g_X [(size_t)TOKENS * HIDDEN];
__device__ __align__(256) int8_t g_W1[(size_t)FFDIM  * HIDDEN];
__device__ __align__(256) int8_t g_W2[(size_t)HIDDEN * FFDIM ];
__device__ __align__(256) int8_t g_H [(size_t)TOKENS * FFDIM ];   // 64MB

// ------------------------- tiling config -------------------------
static constexpr int BM = 128;
static constexpr int BN = 128;
static constexpr int BKB = 128;                     // K elems (int8) per stage
static constexpr int STAGES = 3;
static constexpr int A_TILE = BM * BKB;             // 16384
static constexpr int B_TILE = BN * BKB;             // 16384
static constexpr uint32_t SMEM_BYTES = STAGES * (A_TILE + B_TILE);  // 98304
static constexpr int GROUP_M = 8;
static constexpr int SKEW_CYC = 2000;               // ~half k-iter period

// ------------------------- PTX helpers -------------------------
__device__ __forceinline__ uint32_t s2u(const void* p) {
    uint32_t a;
    asm("{ .reg .u64 t; cvta.to.shared.u64 t, %1; cvt.u32.u64 %0, t; }"
        : "=r"(a) : "l"(p));
    return a;
}

#define CP_ASYNC16(dst, src) \
    asm volatile("cp.async.cg.shared.global [%0], [%1], 16;" :: "r"(dst), "l"(src))
#define CP_COMMIT() asm volatile("cp.async.commit_group;" ::: "memory")
#define CP_WAIT(n)  asm volatile("cp.async.wait_group %0;" :: "n"(n) : "memory")

#define LDM_X4(r0, r1, r2, r3, addr) \
    asm volatile("ldmatrix.sync.aligned.m8n8.x4.shared.b16 {%0,%1,%2,%3}, [%4];" \
        : "=r"(r0), "=r"(r1), "=r"(r2), "=r"(r3) : "r"(addr))

#define MMA_S8(c, a, b0, b1) \
    asm("mma.sync.aligned.m16n8k32.row.col.s32.s8.s8.s32 " \
        "{%0,%1,%2,%3}, {%4,%5,%6,%7}, {%8,%9}, {%0,%1,%2,%3};" \
        : "+r"((c)[0]), "+r"((c)[1]), "+r"((c)[2]), "+r"((c)[3]) \
        : "r"((a)[0]), "r"((a)[1]), "r"((a)[2]), "r"((a)[3]), "r"(b0), "r"(b1))

// 16B-chunk XOR swizzle within a 128B row: conflict-free cp.async + ldmatrix.
__device__ __forceinline__ uint32_t sw(uint32_t row, uint32_t kb) {
    return row * 128u + (((((kb >> 4) ^ row) & 7u)) << 4) + (kb & 15u);
}

// python floor-div by positive constant + clip to [-127, 127]
template<int DIV>
__device__ __forceinline__ int fd(int a) {
    int q = a / DIV;
    q -= (int)((a % DIV != 0) && (a < 0));
    q = q < -127 ? -127 : q;
    q = q >  127 ?  127 : q;
    return q;
}

// ------------------------- GEMM kernel -------------------------
// C = clipdiv(A[M,K]i8 @ B[N,K]i8^T, DIV); C int8 (layer 1) or f32 (layer 2).
// 4 warps as 2x2 grid of 64x64 warp tiles over the 128x128 CTA tile.
template<int DIV, bool F32OUT>
__global__ void __launch_bounds__(128, 2)
gemm_i8(const int8_t* __restrict__ A, const int8_t* __restrict__ B,
        void* __restrict__ Cp, int M, int N, int K)
{
    extern __shared__ char smem[];
    const uint32_t sA = s2u(smem);                  // STAGES * A_TILE
    const uint32_t sB = sA + STAGES * A_TILE;       // STAGES * B_TILE

    // cross-CTA phase offset: odd residency slot starts ~half k-iter later.
    // Slot parity = (bid / 148) & 1 (wave-0 fill order; successors inherit).
    if (((blockIdx.x / 148) & 1) != 0) {
        long long t0 = clock64();
        while (clock64() - t0 < SKEW_CYC) { }
    }

    const int tid  = threadIdx.x;
    const int lane = tid & 31;
    const int wid  = tid >> 5;
    const int wm = (wid >> 1) * 64;     // 2 warp-rows
    const int wn = (wid & 1) * 64;      // 2 warp-cols

    // tile rasterization (GROUP_M supertiles for L2 reuse)
    const int tiles_m = M / BM, tiles_n = N / BN;
    const int bid   = blockIdx.x;
    const int group = GROUP_M * tiles_n;
    const int gi    = bid / group;
    const int first = gi * GROUP_M;
    const int gsz   = min(tiles_m - first, GROUP_M);
    const int inb   = bid % group;
    const int mtile = first + (inb % gsz);
    const int ntile = inb / gsz;

    const int nk = K / BKB;
    const int8_t* Abase = A + (size_t)mtile * BM * K;
    const int8_t* Bbase = B + (size_t)ntile * BN * K;

    auto issue = [&](int kt) {
        const int st = kt % STAGES;
        const uint32_t dA = sA + st * A_TILE;
        const uint32_t dB = sB + st * B_TILE;
        const int k0 = kt * BKB;
        #pragma unroll
        for (int t = 0; t < 8; t++) {               // A: 1024 16B chunks
            int idx = tid + 128 * t;
            int row = idx >> 3;
            int kb  = (idx & 7) << 4;
            CP_ASYNC16(dA + sw(row, kb), Abase + (size_t)row * K + k0 + kb);
        }
        #pragma unroll
        for (int t = 0; t < 8; t++) {               // B: 1024 16B chunks
            int idx = tid + 128 * t;
            int row = idx >> 3;
            int kb  = (idx & 7) << 4;
            CP_ASYNC16(dB + sw(row, kb), Bbase + (size_t)row * K + k0 + kb);
        }
    };

    #pragma unroll
    for (int s = 0; s < STAGES - 1; s++) { issue(s); CP_COMMIT(); }

    int c[4][8][4];                                 // 64x64 -> 4 m16 x 8 n8
    #pragma unroll
    for (int i = 0; i < 4; i++)
        #pragma unroll
        for (int j = 0; j < 8; j++)
            #pragma unroll
            for (int r = 0; r < 4; r++) c[i][j][r] = 0;

    const uint32_t a_row0 = wm + (lane & 15);
    const uint32_t a_kbx  = (uint32_t)((lane >> 4) << 4);
    const uint32_t b_row0 = wn + ((lane >> 4) << 3) + (lane & 7);
    const uint32_t b_kbx  = (uint32_t)(((lane >> 3) & 1) << 4);

    for (int kt = 0; kt < nk; kt++) {
        // last iteration consumes the newest committed group: wait fully.
        if (kt == nk - 1) { CP_WAIT(0); } else { CP_WAIT(STAGES - 2); }
        __syncthreads();

        const uint32_t bA = sA + (kt % STAGES) * A_TILE;
        const uint32_t bB = sB + (kt % STAGES) * B_TILE;
        const int ld = kt + STAGES - 1;

        #pragma unroll
        for (int ks = 0; ks < 4; ks++) {
            uint32_t a[4][4], b[4][4];
            #pragma unroll
            for (int mt = 0; mt < 4; mt++) {        // A: 4 x m16k32
                uint32_t ad = bA + sw(a_row0 + mt * 16, ks * 32 + a_kbx);
                LDM_X4(a[mt][0], a[mt][1], a[mt][2], a[mt][3], ad);
            }
            #pragma unroll
            for (int nh = 0; nh < 4; nh++) {        // B: 4 x n16k32
                uint32_t bd = bB + sw(b_row0 + nh * 16, ks * 32 + b_kbx);
                LDM_X4(b[nh][0], b[nh][1], b[nh][2], b[nh][3], bd);
            }
            // cp.async burst for the next stage: overlaps LDS latency + MMAs.
            if (ks == 0 && ld < nk) { issue(ld); CP_COMMIT(); }
            #pragma unroll
            for (int mt = 0; mt < 4; mt++)
                #pragma unroll
                for (int nt = 0; nt < 8; nt++)
                    MMA_S8(c[mt][nt], a[mt],
                           b[nt >> 1][(nt & 1) * 2],
                           b[nt >> 1][(nt & 1) * 2 + 1]);
        }
    }

    // epilogue: floor-div + clip
    const size_t crow = (size_t)mtile * BM + wm;
    const int    ccol = ntile * BN + wn;
    #pragma unroll
    for (int mt = 0; mt < 4; mt++) {
        #pragma unroll
        for (int nt = 0; nt < 8; nt++) {
            size_t r0  = crow + mt * 16 + (lane >> 2);
            int    col = ccol + nt * 8 + (lane & 3) * 2;
            if (F32OUT) {
                float* Cf = (float*)Cp;
                float2 v0 = make_float2((float)fd<DIV>(c[mt][nt][0]),
                                        (float)fd<DIV>(c[mt][nt][1]));
                float2 v1 = make_float2((float)fd<DIV>(c[mt][nt][2]),
                                        (float)fd<DIV>(c[mt][nt][3]));
                *(float2*)&Cf[r0 * (size_t)N + col] = v0;
                *(float2*)&Cf[(r0 + 8) * (size_t)N + col] = v1;
            } else {
                int8_t* Ci = (int8_t*)Cp;
                int q0 = fd<DIV>(c[mt][nt][0]), q1 = fd<DIV>(c[mt][nt][1]);
                int q2 = fd<DIV>(c[mt][nt][2]), q3 = fd<DIV>(c[mt][nt][3]);
                *(uint16_t*)&Ci[r0 * (size_t)N + col] =
                    (uint16_t)((q0 & 0xFF) | ((q1 & 0xFF) << 8));
                *(uint16_t*)&Ci[(r0 + 8) * (size_t)N + col] =
                    (uint16_t)((q2 & 0xFF) | ((q3 & 0xFF) << 8));
            }
        }
    }
}

// -------- dtype-robust 32-bit-word -> i8 conversion (3 tensors, 1 launch) ----
__device__ __forceinline__ int8_t word_to_i8(uint32_t u) {
    float f = __uint_as_float(u);
    float t = truncf(f);
    bool isf = (fabsf(f) <= 127.0f) && (f == t);   // NaN fails both safely
    int v = isf ? (int)f : (int)u;
    return (int8_t)v;
}

__global__ void cvt_w32_i8_3(const uint4* __restrict__ in0, char4* __restrict__ out0,
                             const uint4* __restrict__ in1, char4* __restrict__ out1,
                             const uint4* __restrict__ in2, char4* __restrict__ out2,
                             int n4) {
    int i = blockIdx.x * blockDim.x + threadIdx.x;
    const uint4* in;
    char4* out;
    int j = i;
    if (i < n4)              { in = in0; out = out0; }
    else if (i < 2 * n4)     { in = in1; out = out1; j = i - n4; }
    else if (i < 3 * n4)     { in = in2; out = out2; j = i - 2 * n4; }
    else return;
    uint4 w = in[j];
    char4 c;
    c.x = word_to_i8(w.x);
    c.y = word_to_i8(w.y);
    c.z = word_to_i8(w.z);
    c.w = word_to_i8(w.w);
    out[j] = c;
}

// ------------------------- host -------------------------
extern "C" void kernel_launch(void* const* d_in, const int* in_sizes, int n_in,
                              void* d_out, int out_size) {
    void *pX, *pW1, *pW2, *pH;
    cudaGetSymbolAddress(&pX,  g_X);
    cudaGetSymbolAddress(&pW1, g_W1);
    cudaGetSymbolAddress(&pW2, g_W2);
    cudaGetSymbolAddress(&pH,  g_H);

    const int n  = TOKENS * HIDDEN;      // all three tensors: 16.7M elements
    const int n4 = n / 4;
    const int cb = (3 * n4 + 255) / 256;
    cvt_w32_i8_3<<<cb, 256>>>((const uint4*)d_in[0], (char4*)pX,
                              (const uint4*)d_in[1], (char4*)pW1,
                              (const uint4*)d_in[2], (char4*)pW2, n4);

    cudaFuncSetAttribute(gemm_i8<720,  false>,
                         cudaFuncAttributeMaxDynamicSharedMemorySize, SMEM_BYTES);
    cudaFuncSetAttribute(gemm_i8<1440, true >,
                         cudaFuncAttributeMaxDynamicSharedMemorySize, SMEM_BYTES);

    // GEMM1: h[8192,8192]i8 = clipdiv(x @ w1^T, 720)
    gemm_i8<720, false><<<(TOKENS / BM) * (FFDIM / BN), 128, SMEM_BYTES>>>(
        (const int8_t*)pX, (const int8_t*)pW1, pH, TOKENS, FFDIM, HIDDEN);

    // GEMM2: out[8192,2048]f32 = clipdiv(h @ w2^T, 1440)
    gemm_i8<1440, true><<<(TOKENS / BM) * (HIDDEN / BN), 128, SMEM_BYTES>>>(
        (const int8_t*)pH, (const int8_t*)pW2, d_out, TOKENS, HIDDEN, FFDIM);
}

// round 16
// speedup vs baseline: 1.0523x; 1.0196x over previous
#include <cuda_runtime.h>
#include <cstdint>

// IntMLP on B200, baseline sm_100 PTX target (no tcgen05 in this harness).
// Inputs: int32 words (robust conversion handles f32 too). Output: float32.
// out = clipdiv(clipdiv(x @ w1^T, 720) @ w2^T, 1440), exact int32 math.
//
// R15 -> R16: LEAN persistent CTAs. Model fit across GEMM1/GEMM2 shows the
// mainloop already runs at 95% of the MMA issue floor (x=2146 cyc/k-iter vs
// 2048 floor); the loss is f~17.6K cyc FIXED per CTA-turn (~170us total).
// R14's persistence targeted f but regressed -- its extra live registers
// (cached next-tile pointers, dual stage counters) pushed past the 255 cap
// into mainloop spills. This version keeps bookkeeping to 6 ints, recomputes
// A/B bases inside issue(), derives the load-stage from the consume-stage.

#define TOKENS 8192
#define HIDDEN 2048
#define FFDIM  8192

// ---------------- device scratch (no allocs allowed) ----------------
__device__ __align__(256) int8_t g_X [(size_t)TOKENS * HIDDEN];
__device__ __align__(256) int8_t g_W1[(size_t)FFDIM  * HIDDEN];
__device__ __align__(256) int8_t g_W2[(size_t)HIDDEN * FFDIM ];
__device__ __align__(256) int8_t g_H [(size_t)TOKENS * FFDIM ];   // 64MB

// ------------------------- tiling config -------------------------
static constexpr int BM = 128;
static constexpr int BN = 128;
static constexpr int BKB = 128;                     // K elems (int8) per stage
static constexpr int STAGES = 3;
static constexpr int A_TILE = BM * BKB;             // 16384
static constexpr int B_TILE = BN * BKB;             // 16384
static constexpr uint32_t SMEM_BYTES = STAGES * (A_TILE + B_TILE);  // 98304
static constexpr int GROUP_M = 8;

// ------------------------- PTX helpers -------------------------
__device__ __forceinline__ uint32_t s2u(const void* p) {
    uint32_t a;
    asm("{ .reg .u64 t; cvta.to.shared.u64 t, %1; cvt.u32.u64 %0, t; }"
        : "=r"(a) : "l"(p));
    return a;
}

#define CP_ASYNC16(dst, src) \
    asm volatile("cp.async.cg.shared.global [%0], [%1], 16;" :: "r"(dst), "l"(src))
#define CP_COMMIT() asm volatile("cp.async.commit_group;" ::: "memory")
#define CP_WAIT(n)  asm volatile("cp.async.wait_group %0;" :: "n"(n) : "memory")

#define LDM_X4(r0, r1, r2, r3, addr) \
    asm volatile("ldmatrix.sync.aligned.m8n8.x4.shared.b16 {%0,%1,%2,%3}, [%4];" \
        : "=r"(r0), "=r"(r1), "=r"(r2), "=r"(r3) : "r"(addr))

#define MMA_S8(c, a, b0, b1) \
    asm("mma.sync.aligned.m16n8k32.row.col.s32.s8.s8.s32 " \
        "{%0,%1,%2,%3}, {%4,%5,%6,%7}, {%8,%9}, {%0,%1,%2,%3};" \
        : "+r"((c)[0]), "+r"((c)[1]), "+r"((c)[2]), "+r"((c)[3]) \
        : "r"((a)[0]), "r"((a)[1]), "r"((a)[2]), "r"((a)[3]), "r"(b0), "r"(b1))

// 16B-chunk XOR swizzle within a 128B row: conflict-free cp.async + ldmatrix.
__device__ __forceinline__ uint32_t sw(uint32_t row, uint32_t kb) {
    return row * 128u + (((((kb >> 4) ^ row) & 7u)) << 4) + (kb & 15u);
}

// python floor-div by positive constant + clip to [-127, 127]
template<int DIV>
__device__ __forceinline__ int fd(int a) {
    int q = a / DIV;
    q -= (int)((a % DIV != 0) && (a < 0));
    q = q < -127 ? -127 : q;
    q = q >  127 ?  127 : q;
    return q;
}

// ------------------------- GEMM kernel -------------------------
// Lean persistent: each CTA walks tiles t = bid, bid+grid, ...; the 3-stage
// cp.async ring rolls across tile boundaries (one cold prologue per CTA).
// C = clipdiv(A[M,K]i8 @ B[N,K]i8^T, DIV); C int8 (layer 1) or f32 (layer 2).
template<int DIV, bool F32OUT, int NK>
__global__ void __launch_bounds__(128, 2)
gemm_i8(const int8_t* __restrict__ A, const int8_t* __restrict__ B,
        void* __restrict__ Cp, int M, int N, int K, int total_tiles)
{
    extern __shared__ char smem[];
    const uint32_t sA = s2u(smem);                  // STAGES * A_TILE
    const uint32_t sB = sA + STAGES * A_TILE;       // STAGES * B_TILE

    const int tid  = threadIdx.x;
    const int lane = tid & 31;
    const int wid  = tid >> 5;
    const int wm = (wid >> 1) * 64;     // 2 warp-rows
    const int wn = (wid & 1) * 64;      // 2 warp-cols
    const int tiles_n = N / BN;
    const int tiles_m = M / BM;

    // GROUP_M supertile rasterization (runs once per tile switch)
    auto rast = [&](int t, int& mt, int& nt) {
        const int group = GROUP_M * tiles_n;
        int gi    = t / group;
        int first = gi * GROUP_M;
        int gsz   = min(tiles_m - first, GROUP_M);
        int inb   = t - gi * group;
        mt = first + (inb % gsz);
        nt = inb / gsz;
    };

    // stage loader: bases recomputed here (1 IMAD each) -> fewer live regs
    auto issue = [&](int mt, int nt, int k0, int st) {
        const int8_t* Ab = A + (size_t)mt * (BM * (size_t)K) + k0;
        const int8_t* Bb = B + (size_t)nt * (BN * (size_t)K) + k0;
        const uint32_t dA = sA + st * A_TILE;
        const uint32_t dB = sB + st * B_TILE;
        #pragma unroll
        for (int u = 0; u < 8; u++) {
            int idx = tid + 128 * u;
            int row = idx >> 3;
            int kb  = (idx & 7) << 4;
            CP_ASYNC16(dA + sw(row, kb), Ab + (size_t)row * K + kb);
        }
        #pragma unroll
        for (int u = 0; u < 8; u++) {
            int idx = tid + 128 * u;
            int row = idx >> 3;
            int kb  = (idx & 7) << 4;
            CP_ASYNC16(dB + sw(row, kb), Bb + (size_t)row * K + kb);
        }
    };

    int t = blockIdx.x;
    if (t >= total_tiles) return;
    int mt, nt;
    rast(t, mt, nt);

    // cold prologue (once per CTA): stages 0,1 of the first tile
    issue(mt, nt, 0,   0); CP_COMMIT();
    issue(mt, nt, BKB, 1); CP_COMMIT();

    int c[4][8][4];                                 // 64x64 -> 4 m16 x 8 n8
    #pragma unroll
    for (int i = 0; i < 4; i++)
        #pragma unroll
        for (int j = 0; j < 8; j++)
            #pragma unroll
            for (int r = 0; r < 4; r++) c[i][j][r] = 0;

    const uint32_t a_row0 = wm + (lane & 15);
    const uint32_t a_kbx  = (uint32_t)((lane >> 4) << 4);
    const uint32_t b_row0 = wn + ((lane >> 4) << 3) + (lane & 7);
    const uint32_t b_kbx  = (uint32_t)(((lane >> 3) & 1) << 4);

    const int NCT = gridDim.x;
    int st = 0;                         // stage to consume (load stage derived)

    for (;;) {
        const int tn = t + NCT;
        int mtn = -1, ntn = -1;
        if (tn < total_tiles) rast(tn, mtn, ntn);

        for (int kt = 0; kt < NK; kt++) {
            // one commit per iteration (incl. 2 prologue) => WAIT(1) is exact
            CP_WAIT(STAGES - 2);
            __syncthreads();

            const uint32_t bA = sA + st * A_TILE;
            const uint32_t bB = sB + st * B_TILE;

            #pragma unroll
            for (int ks = 0; ks < 4; ks++) {
                uint32_t a[4][4], b[4][4];
                #pragma unroll
                for (int mti = 0; mti < 4; mti++) {     // A: 4 x m16k32
                    uint32_t ad = bA + sw(a_row0 + mti * 16, ks * 32 + a_kbx);
                    LDM_X4(a[mti][0], a[mti][1], a[mti][2], a[mti][3], ad);
                }
                #pragma unroll
                for (int nh = 0; nh < 4; nh++) {        // B: 4 x n16k32
                    uint32_t bd = bB + sw(b_row0 + nh * 16, ks * 32 + b_kbx);
                    LDM_X4(b[nh][0], b[nh][1], b[nh][2], b[nh][3], bd);
                }
                if (ks == 0) {
                    const int st2 = (st >= 1) ? st - 1 : st + 2;  // (st+2)%3
                    const int gk  = kt + (STAGES - 1);
                    if (gk < NK)        issue(mt,  nt,  gk * BKB,        st2);
                    else if (mtn >= 0)  issue(mtn, ntn, (gk - NK) * BKB, st2);
                    CP_COMMIT();    // always exactly one commit
                }
                #pragma unroll
                for (int mti = 0; mti < 4; mti++)
                    #pragma unroll
                    for (int nti = 0; nti < 8; nti++)
                        MMA_S8(c[mti][nti], a[mti],
                               b[nti >> 1][(nti & 1) * 2],
                               b[nti >> 1][(nti & 1) * 2 + 1]);
            }
            st = (st == STAGES - 1) ? 0 : st + 1;
        }

        // epilogue (register/global only) overlaps next tile's loads
        {
            const size_t crow = (size_t)mt * BM + wm;
            const int    ccol = nt * BN + wn;
            #pragma unroll
            for (int mti = 0; mti < 4; mti++) {
                #pragma unroll
                for (int nti = 0; nti < 8; nti++) {
                    size_t r0  = crow + mti * 16 + (lane >> 2);
                    int    col = ccol + nti * 8 + (lane & 3) * 2;
                    if (F32OUT) {
                        float* Cf = (float*)Cp;
                        float2 v0 = make_float2((float)fd<DIV>(c[mti][nti][0]),
                                                (float)fd<DIV>(c[mti][nti][1]));
                        float2 v1 = make_float2((float)fd<DIV>(c[mti][nti][2]),
                                                (float)fd<DIV>(c[mti][nti][3]));
                        *(float2*)&Cf[r0 * (size_t)N + col] = v0;
                        *(float2*)&Cf[(r0 + 8) * (size_t)N + col] = v1;
                    } else {
                        int8_t* Ci = (int8_t*)Cp;
                        int q0 = fd<DIV>(c[mti][nti][0]), q1 = fd<DIV>(c[mti][nti][1]);
                        int q2 = fd<DIV>(c[mti][nti][2]), q3 = fd<DIV>(c[mti][nti][3]);
                        *(uint16_t*)&Ci[r0 * (size_t)N + col] =
                            (uint16_t)((q0 & 0xFF) | ((q1 & 0xFF) << 8));
                        *(uint16_t*)&Ci[(r0 + 8) * (size_t)N + col] =
                            (uint16_t)((q2 & 0xFF) | ((q3 & 0xFF) << 8));
                    }
                }
            }
        }

        if (mtn < 0) break;
        #pragma unroll
        for (int i = 0; i < 4; i++)
            #pragma unroll
            for (int j = 0; j < 8; j++)
                #pragma unroll
                for (int r = 0; r < 4; r++) c[i][j][r] = 0;
        t = tn; mt = mtn; nt = ntn;
    }
}

// -------- dtype-robust 32-bit-word -> i8 conversion (3 tensors, 1 launch) ----
__device__ __forceinline__ int8_t word_to_i8(uint32_t u) {
    float f = __uint_as_float(u);
    float t = truncf(f);
    bool isf = (fabsf(f) <= 127.0f) && (f == t);   // NaN fails both safely
    int v = isf ? (int)f : (int)u;
    return (int8_t)v;
}

__global__ void cvt_w32_i8_3(const uint4* __restrict__ in0, char4* __restrict__ out0,
                             const uint4* __restrict__ in1, char4* __restrict__ out1,
                             const uint4* __restrict__ in2, char4* __restrict__ out2,
                             int n4) {
    int i = blockIdx.x * blockDim.x + threadIdx.x;
    const uint4* in;
    char4* out;
    int j = i;
    if (i < n4)              { in = in0; out = out0; }
    else if (i < 2 * n4)     { in = in1; out = out1; j = i - n4; }
    else if (i < 3 * n4)     { in = in2; out = out2; j = i - 2 * n4; }
    else return;
    uint4 w = in[j];
    char4 c;
    c.x = word_to_i8(w.x);
    c.y = word_to_i8(w.y);
    c.z = word_to_i8(w.z);
    c.w = word_to_i8(w.w);
    out[j] = c;
}

// ------------------------- host -------------------------
extern "C" void kernel_launch(void* const* d_in, const int* in_sizes, int n_in,
                              void* d_out, int out_size) {
    void *pX, *pW1, *pW2, *pH;
    cudaGetSymbolAddress(&pX,  g_X);
    cudaGetSymbolAddress(&pW1, g_W1);
    cudaGetSymbolAddress(&pW2, g_W2);
    cudaGetSymbolAddress(&pH,  g_H);

    const int n  = TOKENS * HIDDEN;      // all three tensors: 16.7M elements
    const int n4 = n / 4;
    const int cb = (3 * n4 + 255) / 256;
    cvt_w32_i8_3<<<cb, 256>>>((const uint4*)d_in[0], (char4*)pX,
                              (const uint4*)d_in[1], (char4*)pW1,
                              (const uint4*)d_in[2], (char4*)pW2, n4);

    int sms = 148;
    cudaDeviceGetAttribute(&sms, cudaDevAttrMultiProcessorCount, 0);
    const int slots = 2 * sms;

    cudaFuncSetAttribute(gemm_i8<720,  false, HIDDEN / BKB>,
                         cudaFuncAttributeMaxDynamicSharedMemorySize, SMEM_BYTES);
    cudaFuncSetAttribute(gemm_i8<1440, true,  FFDIM / BKB>,
                         cudaFuncAttributeMaxDynamicSharedMemorySize, SMEM_BYTES);

    // GEMM1: h[8192,8192]i8 = clipdiv(x @ w1^T, 720); 4096 tiles
    {
        const int total = (TOKENS / BM) * (FFDIM / BN);
        const int grid  = slots < total ? slots : total;
        gemm_i8<720, false, HIDDEN / BKB><<<grid, 128, SMEM_BYTES>>>(
            (const int8_t*)pX, (const int8_t*)pW1, pH,
            TOKENS, FFDIM, HIDDEN, total);
    }
    // GEMM2: out[8192,2048]f32 = clipdiv(h @ w2^T, 1440); 1024 tiles
    {
        const int total = (TOKENS / BM) * (HIDDEN / BN);
        const int grid  = slots < total ? slots : total;
        gemm_i8<1440, true, FFDIM / BKB><<<grid, 128, SMEM_BYTES>>>(
            (const int8_t*)pH, (const int8_t*)pW2, d_out,
            TOKENS, HIDDEN, FFDIM, total);
    }
}

// round 17
// speedup vs baseline: 1.0529x; 1.0006x over previous
#include <cuda_runtime.h>
#include <cstdint>

// IntMLP on B200, baseline sm_100 PTX target (no tcgen05 in this harness).
// Inputs: int32 words (robust conversion handles f32 too). Output: float32.
// out = clipdiv(clipdiv(x @ w1^T, 720) @ w2^T, 1440), exact int32 math.
//
// R16 -> R17: I$-thrash fix. The fitted 17.5K-cyc per-tile fixed cost is
// invariant to data-path pipelining/persistence/output-dtype -> instruction
// cache misses from the ~30KB fully-unrolled epilogue, re-missed every tile.
// New epilogue: dump raw int32 accums to smem (tiles dead, 64KB free in the
// non-persistent base), then a ROLLED write-out loop (~3KB total code) with
// conflict-free smem reads and fully-coalesced global stores.

#define TOKENS 8192
#define HIDDEN 2048
#define FFDIM  8192

// ---------------- device scratch (no allocs allowed) ----------------
__device__ __align__(256) int8_t g_X [(size_t)TOKENS * HIDDEN];
__device__ __align__(256) int8_t g_W1[(size_t)FFDIM  * HIDDEN];
__device__ __align__(256) int8_t g_W2[(size_t)HIDDEN * FFDIM ];
__device__ __align__(256) int8_t g_H [(size_t)TOKENS * FFDIM ];   // 64MB

// ------------------------- tiling config -------------------------
static constexpr int BM = 128;
static constexpr int BN = 128;
static constexpr int BKB = 128;                     // K elems (int8) per stage
static constexpr int STAGES = 3;
static constexpr int A_TILE = BM * BKB;             // 16384
static constexpr int B_TILE = BN * BKB;             // 16384
static constexpr uint32_t SMEM_BYTES = STAGES * (A_TILE + B_TILE);  // 98304
static constexpr int GROUP_M = 8;

// ------------------------- PTX helpers -------------------------
__device__ __forceinline__ uint32_t s2u(const void* p) {
    uint32_t a;
    asm("{ .reg .u64 t; cvta.to.shared.u64 t, %1; cvt.u32.u64 %0, t; }"
        : "=r"(a) : "l"(p));
    return a;
}

#define CP_ASYNC16(dst, src) \
    asm volatile("cp.async.cg.shared.global [%0], [%1], 16;" :: "r"(dst), "l"(src))
#define CP_COMMIT() asm volatile("cp.async.commit_group;" ::: "memory")
#define CP_WAIT(n)  asm volatile("cp.async.wait_group %0;" :: "n"(n) : "memory")

#define LDM_X4(r0, r1, r2, r3, addr) \
    asm volatile("ldmatrix.sync.aligned.m8n8.x4.shared.b16 {%0,%1,%2,%3}, [%4];" \
        : "=r"(r0), "=r"(r1), "=r"(r2), "=r"(r3) : "r"(addr))

#define MMA_S8(c, a, b0, b1) \
    asm("mma.sync.aligned.m16n8k32.row.col.s32.s8.s8.s32 " \
        "{%0,%1,%2,%3}, {%4,%5,%6,%7}, {%8,%9}, {%0,%1,%2,%3};" \
        : "+r"((c)[0]), "+r"((c)[1]), "+r"((c)[2]), "+r"((c)[3]) \
        : "r"((a)[0]), "r"((a)[1]), "r"((a)[2]), "r"((a)[3]), "r"(b0), "r"(b1))

// 16B-chunk XOR swizzle within a 128B row: conflict-free cp.async + ldmatrix.
__device__ __forceinline__ uint32_t sw(uint32_t row, uint32_t kb) {
    return row * 128u + (((((kb >> 4) ^ row) & 7u)) << 4) + (kb & 15u);
}

// python floor-div by positive constant + clip to [-127, 127]
template<int DIV>
__device__ __forceinline__ int fd(int a) {
    int q = a / DIV;
    q -= (int)((a % DIV != 0) && (a < 0));
    q = q < -127 ? -127 : q;
    q = q >  127 ?  127 : q;
    return q;
}

// ------------------------- GEMM kernel -------------------------
// C = clipdiv(A[M,K]i8 @ B[N,K]i8^T, DIV); C int8 (layer 1) or f32 (layer 2).
// 4 warps as 2x2 grid of 64x64 warp tiles over the 128x128 CTA tile.
template<int DIV, bool F32OUT>
__global__ void __launch_bounds__(128, 2)
gemm_i8(const int8_t* __restrict__ A, const int8_t* __restrict__ B,
        void* __restrict__ Cp, int M, int N, int K)
{
    extern __shared__ char smem[];
    const uint32_t sA = s2u(smem);                  // STAGES * A_TILE
    const uint32_t sB = sA + STAGES * A_TILE;       // STAGES * B_TILE

    const int tid  = threadIdx.x;
    const int lane = tid & 31;
    const int wid  = tid >> 5;
    const int wm = (wid >> 1) * 64;     // 2 warp-rows
    const int wn = (wid & 1) * 64;      // 2 warp-cols

    // tile rasterization (GROUP_M supertiles for L2 reuse)
    const int tiles_m = M / BM, tiles_n = N / BN;
    const int bid   = blockIdx.x;
    const int group = GROUP_M * tiles_n;
    const int gi    = bid / group;
    const int first = gi * GROUP_M;
    const int gsz   = min(tiles_m - first, GROUP_M);
    const int inb   = bid % group;
    const int mtile = first + (inb % gsz);
    const int ntile = inb / gsz;

    const int nk = K / BKB;
    const int8_t* Abase = A + (size_t)mtile * BM * K;
    const int8_t* Bbase = B + (size_t)ntile * BN * K;

    auto issue = [&](int kt) {
        const int st = kt % STAGES;
        const uint32_t dA = sA + st * A_TILE;
        const uint32_t dB = sB + st * B_TILE;
        const int k0 = kt * BKB;
        #pragma unroll
        for (int t = 0; t < 8; t++) {               // A: 1024 16B chunks
            int idx = tid + 128 * t;
            int row = idx >> 3;
            int kb  = (idx & 7) << 4;
            CP_ASYNC16(dA + sw(row, kb), Abase + (size_t)row * K + k0 + kb);
        }
        #pragma unroll
        for (int t = 0; t < 8; t++) {               // B: 1024 16B chunks
            int idx = tid + 128 * t;
            int row = idx >> 3;
            int kb  = (idx & 7) << 4;
            CP_ASYNC16(dB + sw(row, kb), Bbase + (size_t)row * K + k0 + kb);
        }
    };

    #pragma unroll
    for (int s = 0; s < STAGES - 1; s++) { issue(s); CP_COMMIT(); }

    int c[4][8][4];                                 // 64x64 -> 4 m16 x 8 n8
    #pragma unroll
    for (int i = 0; i < 4; i++)
        #pragma unroll
        for (int j = 0; j < 8; j++)
            #pragma unroll
            for (int r = 0; r < 4; r++) c[i][j][r] = 0;

    const uint32_t a_row0 = wm + (lane & 15);
    const uint32_t a_kbx  = (uint32_t)((lane >> 4) << 4);
    const uint32_t b_row0 = wn + ((lane >> 4) << 3) + (lane & 7);
    const uint32_t b_kbx  = (uint32_t)(((lane >> 3) & 1) << 4);

    for (int kt = 0; kt < nk; kt++) {
        // last iteration consumes the newest committed group: wait fully.
        if (kt == nk - 1) { CP_WAIT(0); } else { CP_WAIT(STAGES - 2); }
        __syncthreads();

        const uint32_t bA = sA + (kt % STAGES) * A_TILE;
        const uint32_t bB = sB + (kt % STAGES) * B_TILE;
        const int ld = kt + STAGES - 1;

        #pragma unroll
        for (int ks = 0; ks < 4; ks++) {
            uint32_t a[4][4], b[4][4];
            #pragma unroll
            for (int mt = 0; mt < 4; mt++) {        // A: 4 x m16k32
                uint32_t ad = bA + sw(a_row0 + mt * 16, ks * 32 + a_kbx);
                LDM_X4(a[mt][0], a[mt][1], a[mt][2], a[mt][3], ad);
            }
            #pragma unroll
            for (int nh = 0; nh < 4; nh++) {        // B: 4 x n16k32
                uint32_t bd = bB + sw(b_row0 + nh * 16, ks * 32 + b_kbx);
                LDM_X4(b[nh][0], b[nh][1], b[nh][2], b[nh][3], bd);
            }
            // cp.async burst for the next stage: overlaps LDS latency + MMAs.
            if (ks == 0 && ld < nk) { issue(ld); CP_COMMIT(); }
            #pragma unroll
            for (int mt = 0; mt < 4; mt++)
                #pragma unroll
                for (int nt = 0; nt < 8; nt++)
                    MMA_S8(c[mt][nt], a[mt],
                           b[nt >> 1][(nt & 1) * 2],
                           b[nt >> 1][(nt & 1) * 2 + 1]);
        }
    }

    // ---------------- epilogue v2: smem-staged, small code ----------------
    __syncthreads();    // all warps done reading tile smem

    // 1) dump raw int32 accumulators to smem, [row][col] 128x128 (64KB)
    //    c[mt][nt][r] -> row = wm + mt*16 + (lane>>2) + (r>=2 ? 8 : 0)
    //                    col = wn + nt*8 + (lane&3)*2 + (r&1)
    {
        char* dump = smem + ((wm + (lane >> 2)) * 128 + wn + (lane & 3) * 2) * 4;
        #pragma unroll
        for (int mt = 0; mt < 4; mt++)
            #pragma unroll
            for (int nt = 0; nt < 8; nt++) {
                char* p = dump + (mt * 16 * 128 + nt * 8) * 4;
                *(int*)(p)                  = c[mt][nt][0];
                *(int*)(p + 4)              = c[mt][nt][1];
                *(int*)(p + 8 * 128 * 4)    = c[mt][nt][2];
                *(int*)(p + 8 * 128 * 4 + 4)= c[mt][nt][3];
            }
    }
    __syncthreads();

    // 2) rolled write-out: iter i -> 512 ints (4 rows); warp w owns one row,
    //    lanes sweep the row contiguously (conflict-free LDS, coalesced STG).
    if (F32OUT) {
        float* Cf = (float*)Cp;
        #pragma unroll 1
        for (int i = 0; i < 32; i++) {
            int idx = i * 512 + tid * 4;            // int index into 128x128
            int row = idx >> 7, col = idx & 127;
            int4 v = *(int4*)(smem + idx * 4);
            float4 o = make_float4((float)fd<DIV>(v.x), (float)fd<DIV>(v.y),
                                   (float)fd<DIV>(v.z), (float)fd<DIV>(v.w));
            *(float4*)&Cf[(size_t)(mtile * BM + row) * N + ntile * BN + col] = o;
        }
    } else {
        int8_t* Ci = (int8_t*)Cp;
        #pragma unroll 1
        for (int i = 0; i < 32; i++) {
            int idx = i * 512 + tid * 4;
            int row = idx >> 7, col = idx & 127;
            int4 v = *(int4*)(smem + idx * 4);
            uint32_t pk = (uint32_t)(fd<DIV>(v.x) & 0xFF)
                        | ((uint32_t)(fd<DIV>(v.y) & 0xFF) << 8)
                        | ((uint32_t)(fd<DIV>(v.z) & 0xFF) << 16)
                        | ((uint32_t)(fd<DIV>(v.w) & 0xFF) << 24);
            *(uint32_t*)&Ci[(size_t)(mtile * BM + row) * N + ntile * BN + col] = pk;
        }
    }
}

// -------- dtype-robust 32-bit-word -> i8 conversion (3 tensors, 1 launch) ----
__device__ __forceinline__ int8_t word_to_i8(uint32_t u) {
    float f = __uint_as_float(u);
    float t = truncf(f);
    bool isf = (fabsf(f) <= 127.0f) && (f == t);   // NaN fails both safely
    int v = isf ? (int)f : (int)u;
    return (int8_t)v;
}

__global__ void cvt_w32_i8_3(const uint4* __restrict__ in0, char4* __restrict__ out0,
                             const uint4* __restrict__ in1, char4* __restrict__ out1,
                             const uint4* __restrict__ in2, char4* __restrict__ out2,
                             int n4) {
    int i = blockIdx.x * blockDim.x + threadIdx.x;
    const uint4* in;
    char4* out;
    int j = i;
    if (i < n4)              { in = in0; out = out0; }
    else if (i < 2 * n4)     { in = in1; out = out1; j = i - n4; }
    else if (i < 3 * n4)     { in = in2; out = out2; j = i - 2 * n4; }
    else return;
    uint4 w = in[j];
    char4 c;
    c.x = word_to_i8(w.x);
    c.y = word_to_i8(w.y);
    c.z = word_to_i8(w.z);
    c.w = word_to_i8(w.w);
    out[j] = c;
}

// ------------------------- host -------------------------
extern "C" void kernel_launch(void* const* d_in, const int* in_sizes, int n_in,
                              void* d_out, int out_size) {
    void *pX, *pW1, *pW2, *pH;
    cudaGetSymbolAddress(&pX,  g_X);
    cudaGetSymbolAddress(&pW1, g_W1);
    cudaGetSymbolAddress(&pW2, g_W2);
    cudaGetSymbolAddress(&pH,  g_H);

    const int n  = TOKENS * HIDDEN;      // all three tensors: 16.7M elements
    const int n4 = n / 4;
    const int cb = (3 * n4 + 255) / 256;
    cvt_w32_i8_3<<<cb, 256>>>((const uint4*)d_in[0], (char4*)pX,
                              (const uint4*)d_in[1], (char4*)pW1,
                              (const uint4*)d_in[2], (char4*)pW2, n4);

    cudaFuncSetAttribute(gemm_i8<720,  false>,
                         cudaFuncAttributeMaxDynamicSharedMemorySize, SMEM_BYTES);
    cudaFuncSetAttribute(gemm_i8<1440, true >,
                         cudaFuncAttributeMaxDynamicSharedMemorySize, SMEM_BYTES);

    // GEMM1: h[8192,8192]i8 = clipdiv(x @ w1^T, 720)
    gemm_i8<720, false><<<(TOKENS / BM) * (FFDIM / BN), 128, SMEM_BYTES>>>(
        (const int8_t*)pX, (const int8_t*)pW1, pH, TOKENS, FFDIM, HIDDEN);

    // GEMM2: out[8192,2048]f32 = clipdiv(h @ w2^T, 1440)
    gemm_i8<1440, true><<<(TOKENS / BM) * (HIDDEN / BN), 128, SMEM_BYTES>>>(
        (const int8_t*)pH, (const int8_t*)pW2, d_out, TOKENS, HIDDEN, FFDIM);
}